// round 2
// baseline (speedup 1.0000x reference)
#include <cuda_runtime.h>
#include <cuda_bf16.h>

// ---------------- problem constants ----------------
#define BATCH 4
#define TTOK 2048
#define DIM 2048
#define DIMV 1024
#define INNER 1024
#define HEADS 16
#define DHEAD 64
#define NMEDIA 8
#define NVIS 64
#define JTOT (NMEDIA * NVIS)   // 512
#define LN_EPS 1e-5f
#define QSCALE 0.125f          // 64^-0.5

// ---------------- scratch (static device memory; no allocs allowed) ----------
__device__ float g_yn[(size_t)BATCH * TTOK * DIM];      // 67 MB
__device__ float g_q[(size_t)BATCH * TTOK * INNER];     // 33.5 MB
__device__ float g_kv[(size_t)BATCH * JTOT * 2 * INNER];// 16.8 MB
__device__ float g_attn[(size_t)BATCH * TTOK * INNER];  // 33.5 MB
__device__ int   g_tt[BATCH * TTOK];

// ---------------- LayerNorm ----------------
__global__ void ln_kernel(const float* __restrict__ y,
                          const float* __restrict__ w,
                          const float* __restrict__ bb,
                          float* __restrict__ yn)
{
    long row = blockIdx.x;
    const float* x = y + row * DIM;
    float sum = 0.f, sq = 0.f;
    for (int i = threadIdx.x; i < DIM; i += 256) {
        float v = x[i];
        sum += v; sq += v * v;
    }
    __shared__ float s1[256], s2[256];
    s1[threadIdx.x] = sum; s2[threadIdx.x] = sq;
    __syncthreads();
    for (int o = 128; o > 0; o >>= 1) {
        if (threadIdx.x < o) { s1[threadIdx.x] += s1[threadIdx.x + o]; s2[threadIdx.x] += s2[threadIdx.x + o]; }
        __syncthreads();
    }
    float mu = s1[0] * (1.0f / DIM);
    float var = s2[0] * (1.0f / DIM) - mu * mu;
    float rstd = rsqrtf(var + LN_EPS);
    float* o = yn + row * DIM;
    for (int i = threadIdx.x; i < DIM; i += 256)
        o[i] = (x[i] - mu) * rstd * w[i] + bb[i];
}

// ---------------- text_time = cumsum(media_locations) ----------------
// media_locations is a bool array in the reference; the harness materializes
// it as a 4-byte type (int32 0/1 or float32 0.0/1.0). Reading 32-bit words and
// testing "nonzero" is correct for both encodings.
__global__ void cumsum_kernel(const unsigned int* __restrict__ loc, int* __restrict__ tt)
{
    int b = threadIdx.x;
    if (b < BATCH) {
        int s = 0;
        for (int t = 0; t < TTOK; t++) {
            s += (loc[b * TTOK + t] != 0u) ? 1 : 0;
            tt[b * TTOK + t] = s;
        }
    }
}

// ---------------- fp32 tiled GEMM: C[M,N] = alpha * A[M,K] @ B[K,N] ---------
#define BM 128
#define BN 128
#define BKK 16
#define TM 8
#define TN 8

__global__ __launch_bounds__(256, 2)
void sgemm128(const float* __restrict__ A, const float* __restrict__ B,
              float* __restrict__ C, int M, int N, int K, float alpha)
{
    __shared__ float As[BKK][BM];
    __shared__ float Bs[BKK][BN];

    int tid = threadIdx.x;          // 0..255
    int block_row = blockIdx.y * BM;
    int block_col = blockIdx.x * BN;
    int tr = tid / 16;              // 0..15
    int tc = tid % 16;              // 0..15

    float acc[TM][TN];
    #pragma unroll
    for (int i = 0; i < TM; i++)
        #pragma unroll
        for (int j = 0; j < TN; j++) acc[i][j] = 0.f;

    for (int k0 = 0; k0 < K; k0 += BKK) {
        #pragma unroll
        for (int i = 0; i < 2; i++) {
            int id = tid * 2 + i;
            // A tile: 128 rows x 16 cols = 512 float4 (4 per row)
            int ar = id >> 2, ac4 = id & 3;
            float4 a = *(const float4*)&A[(long)(block_row + ar) * K + k0 + ac4 * 4];
            As[ac4 * 4 + 0][ar] = a.x;
            As[ac4 * 4 + 1][ar] = a.y;
            As[ac4 * 4 + 2][ar] = a.z;
            As[ac4 * 4 + 3][ar] = a.w;
            // B tile: 16 rows x 128 cols = 512 float4 (32 per row)
            int br = id >> 5, bc4 = id & 31;
            float4 bv = *(const float4*)&B[(long)(k0 + br) * N + block_col + bc4 * 4];
            *(float4*)&Bs[br][bc4 * 4] = bv;
        }
        __syncthreads();
        #pragma unroll
        for (int k = 0; k < BKK; k++) {
            float ra[TM], rb[TN];
            *(float4*)&ra[0] = *(const float4*)&As[k][tr * TM];
            *(float4*)&ra[4] = *(const float4*)&As[k][tr * TM + 4];
            *(float4*)&rb[0] = *(const float4*)&Bs[k][tc * TN];
            *(float4*)&rb[4] = *(const float4*)&Bs[k][tc * TN + 4];
            #pragma unroll
            for (int i = 0; i < TM; i++)
                #pragma unroll
                for (int j = 0; j < TN; j++)
                    acc[i][j] += ra[i] * rb[j];
        }
        __syncthreads();
    }

    #pragma unroll
    for (int i = 0; i < TM; i++) {
        long row = block_row + tr * TM + i;
        #pragma unroll
        for (int j = 0; j < TN; j += 4) {
            float4 o;
            o.x = alpha * acc[i][j + 0];
            o.y = alpha * acc[i][j + 1];
            o.z = alpha * acc[i][j + 2];
            o.w = alpha * acc[i][j + 3];
            *(float4*)&C[row * N + block_col + tc * TN + j] = o;
        }
    }
}

// ---------------- masked attention --------------------------------------
// grid (NMEDIA, HEADS, BATCH). Each CTA holds K,V for one (b, h, media block)
// in SMEM (64 keys x 64 dims each) and serves every token whose text_time
// selects that media block. Softmax is over exactly those 64 keys (masked-out
// keys contribute exp(-inf)=0 in the reference). text_time==0 or >NMEDIA
// (empty mask) falls back to a uniform average over all 512 v (reference
// softmax of all -FLT_MAX rows).
__global__ __launch_bounds__(256)
void attn_kernel(const float* __restrict__ q, const float* __restrict__ kv,
                 const int* __restrict__ tt, float* __restrict__ out)
{
    __shared__ float Ks[64][65];
    __shared__ float Vs[64][65];
    int m = blockIdx.x;
    int h = blockIdx.y;
    int b = blockIdx.z;
    int tid = threadIdx.x;

    const float* kvb = kv + (long)b * JTOT * (2 * INNER);
    for (int idx = tid; idx < 64 * 64; idx += 256) {
        int j = idx >> 6, d = idx & 63;
        long base = (long)(m * 64 + j) * (2 * INNER) + h * DHEAD + d;
        Ks[j][d] = kvb[base];
        Vs[j][d] = kvb[base + INNER];
    }
    __syncthreads();

    int warp = tid >> 5, lane = tid & 31;
    const unsigned FULL = 0xffffffffu;

    for (int t = warp; t < TTOK; t += 8) {
        int t_time = tt[b * TTOK + t];
        bool empty = (t_time < 1 || t_time > NMEDIA);
        long qb = ((long)(b * TTOK + t)) * INNER + h * DHEAD;

        if (empty) {
            if (m == 0) {  // handled once
                float o0 = 0.f, o1 = 0.f;
                for (int j = 0; j < JTOT; j++) {
                    o0 += kvb[(long)j * (2 * INNER) + INNER + h * DHEAD + lane];
                    o1 += kvb[(long)j * (2 * INNER) + INNER + h * DHEAD + 32 + lane];
                }
                out[qb + lane] = o0 * (1.0f / JTOT);
                out[qb + 32 + lane] = o1 * (1.0f / JTOT);
            }
            continue;
        }
        if (t_time != m + 1) continue;

        float q0 = q[qb + lane];
        float q1 = q[qb + 32 + lane];

        float s0 = 0.f, s1 = 0.f;
        #pragma unroll
        for (int d = 0; d < 32; d++) {
            float qd = __shfl_sync(FULL, q0, d);
            s0 += qd * Ks[lane][d];
            s1 += qd * Ks[lane + 32][d];
        }
        #pragma unroll
        for (int d = 0; d < 32; d++) {
            float qd = __shfl_sync(FULL, q1, d);
            s0 += qd * Ks[lane][32 + d];
            s1 += qd * Ks[lane + 32][32 + d];
        }

        float mx = fmaxf(s0, s1);
        #pragma unroll
        for (int o = 16; o > 0; o >>= 1) mx = fmaxf(mx, __shfl_xor_sync(FULL, mx, o));
        float p0 = __expf(s0 - mx);
        float p1 = __expf(s1 - mx);
        float sm = p0 + p1;
        #pragma unroll
        for (int o = 16; o > 0; o >>= 1) sm += __shfl_xor_sync(FULL, sm, o);
        float inv = 1.0f / sm;
        p0 *= inv; p1 *= inv;

        float o0 = 0.f, o1 = 0.f;
        #pragma unroll
        for (int j = 0; j < 32; j++) {
            float pj = __shfl_sync(FULL, p0, j);
            o0 += pj * Vs[j][lane];
            o1 += pj * Vs[j][32 + lane];
        }
        #pragma unroll
        for (int j = 0; j < 32; j++) {
            float pj = __shfl_sync(FULL, p1, j);
            o0 += pj * Vs[32 + j][lane];
            o1 += pj * Vs[32 + j][32 + lane];
        }
        out[qb + lane] = o0;
        out[qb + 32 + lane] = o1;
    }
}

// ---------------- launch --------------------------------------------------
extern "C" void kernel_launch(void* const* d_in, const int* in_sizes, int n_in,
                              void* d_out, int out_size)
{
    const float* y    = (const float*)d_in[0];
    const float* media= (const float*)d_in[1];
    const unsigned int* loc = (const unsigned int*)d_in[2];
    const float* ln_w = (const float*)d_in[3];
    const float* ln_b = (const float*)d_in[4];
    const float* Wq   = (const float*)d_in[5];
    const float* Wkv  = (const float*)d_in[6];
    const float* Wout = (const float*)d_in[7];
    float* out = (float*)d_out;

    float *yn_p, *q_p, *kv_p, *attn_p;
    int* tt_p;
    cudaGetSymbolAddress((void**)&yn_p,  g_yn);
    cudaGetSymbolAddress((void**)&q_p,   g_q);
    cudaGetSymbolAddress((void**)&kv_p,  g_kv);
    cudaGetSymbolAddress((void**)&attn_p,g_attn);
    cudaGetSymbolAddress((void**)&tt_p,  g_tt);

    // 1) LayerNorm
    ln_kernel<<<BATCH * TTOK, 256>>>(y, ln_w, ln_b, yn_p);
    // 2) text_time
    cumsum_kernel<<<1, 32>>>(loc, tt_p);
    // 3) kv = media @ Wkv   [B*J, DIMV] @ [DIMV, 2*INNER]
    {
        dim3 grid((2 * INNER) / BN, (BATCH * JTOT) / BM);
        sgemm128<<<grid, 256>>>(media, Wkv, kv_p, BATCH * JTOT, 2 * INNER, DIMV, 1.0f);
    }
    // 4) q = (yn @ Wq) * scale   [B*T, DIM] @ [DIM, INNER]
    {
        dim3 grid(INNER / BN, (BATCH * TTOK) / BM);
        sgemm128<<<grid, 256>>>(yn_p, Wq, q_p, BATCH * TTOK, INNER, DIM, QSCALE);
    }
    // 5) attention
    {
        dim3 grid(NMEDIA, HEADS, BATCH);
        attn_kernel<<<grid, 256>>>(q_p, kv_p, tt_p, attn_p);
    }
    // 6) out = attn @ Wout   [B*T, INNER] @ [INNER, DIM]
    {
        dim3 grid(DIM / BN, (BATCH * TTOK) / BM);
        sgemm128<<<grid, 256>>>(attn_p, Wout, out, BATCH * TTOK, DIM, INNER, 1.0f);
    }
}

// round 3
// speedup vs baseline: 2.5519x; 2.5519x over previous
#include <cuda_runtime.h>
#include <cuda_bf16.h>
#include <cstdint>

// ---------------- problem constants ----------------
#define BATCH 4
#define TTOK 2048
#define DIM 2048
#define DIMV 1024
#define INNER 1024
#define HEADS 16
#define DHEAD 64
#define NMEDIA 8
#define NVIS 64
#define JTOT (NMEDIA * NVIS)   // 512
#define LN_EPS 1e-5f
#define QSCALE 0.125f          // 64^-0.5

// ---------------- scratch (static device memory; no allocs allowed) ----------
__device__ float g_yn[(size_t)BATCH * TTOK * DIM];      // 67 MB
__device__ float g_q[(size_t)BATCH * TTOK * INNER];     // 33.5 MB
__device__ float g_kv[(size_t)BATCH * JTOT * 2 * INNER];// 16.8 MB
__device__ float g_attn[(size_t)BATCH * TTOK * INNER];  // 33.5 MB
__device__ int   g_tt[BATCH * TTOK];

// ---------------- LayerNorm ----------------
__global__ void ln_kernel(const float* __restrict__ y,
                          const float* __restrict__ w,
                          const float* __restrict__ bb,
                          float* __restrict__ yn)
{
    long row = blockIdx.x;
    const float* x = y + row * DIM;
    float sum = 0.f, sq = 0.f;
    for (int i = threadIdx.x; i < DIM; i += 256) {
        float v = x[i];
        sum += v; sq += v * v;
    }
    __shared__ float s1[256], s2[256];
    s1[threadIdx.x] = sum; s2[threadIdx.x] = sq;
    __syncthreads();
    for (int o = 128; o > 0; o >>= 1) {
        if (threadIdx.x < o) { s1[threadIdx.x] += s1[threadIdx.x + o]; s2[threadIdx.x] += s2[threadIdx.x + o]; }
        __syncthreads();
    }
    float mu = s1[0] * (1.0f / DIM);
    float var = s2[0] * (1.0f / DIM) - mu * mu;
    float rstd = rsqrtf(var + LN_EPS);
    float* o = yn + row * DIM;
    for (int i = threadIdx.x; i < DIM; i += 256)
        o[i] = (x[i] - mu) * rstd * w[i] + bb[i];
}

// ---------------- text_time = cumsum(media_locations) ----------------
__global__ void cumsum_kernel(const unsigned int* __restrict__ loc, int* __restrict__ tt)
{
    int b = threadIdx.x;
    if (b < BATCH) {
        int s = 0;
        for (int t = 0; t < TTOK; t++) {
            s += (loc[b * TTOK + t] != 0u) ? 1 : 0;
            tt[b * TTOK + t] = s;
        }
    }
}

// ---------------- tf32 tensor-core GEMM -----------------------------------
// C[M,N] = alpha * A[M,K] @ B[K,N], fp32 in/out, tf32 MMA (m16n8k8).
// 128x128 CTA tile, K-tile 32, 8 warps in 2x4, 64x32 per warp.
// SMEM padded strides: A stride 36 floats, B stride 136 floats -> fragment
// LDS bank = (4g+tig) / (8*tig+g) mod 32 -> conflict-free.

#define SA 36           // A smem row stride (floats)
#define SB 136          // B smem row stride (floats)
#define A_BUF (128 * SA)          // 4608 floats
#define B_BUF (32 * SB)           // 4352 floats
#define SMEM_FLOATS (2 * (A_BUF + B_BUF))   // 17920 floats = 71680 B

#define CP_ASYNC16(s, g) asm volatile("cp.async.cg.shared.global [%0], [%1], 16;\n" :: "r"(s), "l"(g))
#define CP_COMMIT()      asm volatile("cp.async.commit_group;\n")
#define CP_WAIT0()       asm volatile("cp.async.wait_group 0;\n" ::: "memory")

__device__ __forceinline__ uint32_t f2tf32(float x) {
    uint32_t u;
    asm("cvt.rna.tf32.f32 %0, %1;" : "=r"(u) : "f"(x));
    return u;
}

__global__ __launch_bounds__(256, 2)
void tf32gemm(const float* __restrict__ A, const float* __restrict__ B,
              float* __restrict__ C, int M, int N, int K, float alpha)
{
    extern __shared__ float sm[];
    const int tid  = threadIdx.x;
    const int warp = tid >> 5, lane = tid & 31;
    const int g    = lane >> 2, tig = lane & 3;
    const int wm   = (warp >> 2) * 64;    // 0 / 64
    const int wn   = (warp & 3) * 32;     // 0..96
    const long bm  = (long)blockIdx.y * 128;
    const long bn  = (long)blockIdx.x * 128;

    float acc[4][4][4];
    #pragma unroll
    for (int i = 0; i < 4; i++)
        #pragma unroll
        for (int j = 0; j < 4; j++)
            #pragma unroll
            for (int c = 0; c < 4; c++) acc[i][j][c] = 0.f;

    const int nt = K / 32;

    // ---- async tile loader ----
    auto loadTile = [&](int kt, int buf) {
        const float* Ag = A + bm * K + (long)kt * 32;
        const float* Bg = B + (long)kt * 32 * N + bn;
        float* sA = sm + buf * A_BUF;
        float* sB = sm + 2 * A_BUF + buf * B_BUF;
        #pragma unroll
        for (int t = 0; t < 4; t++) {
            int i = tid + t * 256;          // 0..1023
            int r = i >> 3, c = (i & 7) * 4;
            uint32_t sa = (uint32_t)__cvta_generic_to_shared(sA + r * SA + c);
            CP_ASYNC16(sa, Ag + (long)r * K + c);
        }
        #pragma unroll
        for (int t = 0; t < 4; t++) {
            int i = tid + t * 256;
            int r = i >> 5, c = (i & 31) * 4;
            uint32_t sb = (uint32_t)__cvta_generic_to_shared(sB + r * SB + c);
            CP_ASYNC16(sb, Bg + (long)r * N + c);
        }
    };

    loadTile(0, 0);
    CP_COMMIT();

    int buf = 0;
    for (int kt = 0; kt < nt; kt++) {
        CP_WAIT0();
        __syncthreads();
        if (kt + 1 < nt) { loadTile(kt + 1, buf ^ 1); CP_COMMIT(); }

        const float* sA = sm + buf * A_BUF;
        const float* sB = sm + 2 * A_BUF + buf * B_BUF;

        #pragma unroll
        for (int ks = 0; ks < 4; ks++) {
            const int k0 = ks * 8;
            uint32_t af[4][4], bf[4][2];
            #pragma unroll
            for (int mi = 0; mi < 4; mi++) {
                const float* ar = sA + (wm + mi * 16 + g) * SA + k0;
                af[mi][0] = f2tf32(ar[tig]);
                af[mi][2] = f2tf32(ar[tig + 4]);
                const float* ar2 = ar + 8 * SA;
                af[mi][1] = f2tf32(ar2[tig]);
                af[mi][3] = f2tf32(ar2[tig + 4]);
            }
            #pragma unroll
            for (int ni = 0; ni < 4; ni++) {
                const float* bc = sB + (k0 + tig) * SB + wn + ni * 8 + g;
                bf[ni][0] = f2tf32(bc[0]);
                bf[ni][1] = f2tf32(bc[4 * SB]);
            }
            #pragma unroll
            for (int mi = 0; mi < 4; mi++)
                #pragma unroll
                for (int ni = 0; ni < 4; ni++) {
                    asm volatile(
                        "mma.sync.aligned.m16n8k8.row.col.f32.tf32.tf32.f32 "
                        "{%0,%1,%2,%3}, {%4,%5,%6,%7}, {%8,%9}, {%0,%1,%2,%3};"
                        : "+f"(acc[mi][ni][0]), "+f"(acc[mi][ni][1]),
                          "+f"(acc[mi][ni][2]), "+f"(acc[mi][ni][3])
                        : "r"(af[mi][0]), "r"(af[mi][1]), "r"(af[mi][2]), "r"(af[mi][3]),
                          "r"(bf[ni][0]), "r"(bf[ni][1]));
                }
        }
        __syncthreads();
        buf ^= 1;
    }

    // ---- epilogue ----
    #pragma unroll
    for (int mi = 0; mi < 4; mi++) {
        long r0 = bm + wm + mi * 16 + g;
        #pragma unroll
        for (int ni = 0; ni < 4; ni++) {
            long c0 = bn + wn + ni * 8 + tig * 2;
            float2 v0 = { alpha * acc[mi][ni][0], alpha * acc[mi][ni][1] };
            float2 v1 = { alpha * acc[mi][ni][2], alpha * acc[mi][ni][3] };
            *(float2*)&C[r0 * N + c0]       = v0;
            *(float2*)&C[(r0 + 8) * N + c0] = v1;
        }
    }
}

// ---------------- masked attention --------------------------------------
__global__ __launch_bounds__(256)
void attn_kernel(const float* __restrict__ q, const float* __restrict__ kv,
                 const int* __restrict__ tt, float* __restrict__ out)
{
    __shared__ float Ks[64][65];
    __shared__ float Vs[64][65];
    int m = blockIdx.x;
    int h = blockIdx.y;
    int b = blockIdx.z;
    int tid = threadIdx.x;

    const float* kvb = kv + (long)b * JTOT * (2 * INNER);
    for (int idx = tid; idx < 64 * 64; idx += 256) {
        int j = idx >> 6, d = idx & 63;
        long base = (long)(m * 64 + j) * (2 * INNER) + h * DHEAD + d;
        Ks[j][d] = kvb[base];
        Vs[j][d] = kvb[base + INNER];
    }
    __syncthreads();

    int warp = tid >> 5, lane = tid & 31;
    const unsigned FULL = 0xffffffffu;

    for (int t = warp; t < TTOK; t += 8) {
        int t_time = tt[b * TTOK + t];
        bool empty = (t_time < 1 || t_time > NMEDIA);
        long qb = ((long)(b * TTOK + t)) * INNER + h * DHEAD;

        if (empty) {
            if (m == 0) {
                float o0 = 0.f, o1 = 0.f;
                for (int j = 0; j < JTOT; j++) {
                    o0 += kvb[(long)j * (2 * INNER) + INNER + h * DHEAD + lane];
                    o1 += kvb[(long)j * (2 * INNER) + INNER + h * DHEAD + 32 + lane];
                }
                out[qb + lane] = o0 * (1.0f / JTOT);
                out[qb + 32 + lane] = o1 * (1.0f / JTOT);
            }
            continue;
        }
        if (t_time != m + 1) continue;

        float q0 = q[qb + lane];
        float q1 = q[qb + 32 + lane];

        float s0 = 0.f, s1 = 0.f;
        #pragma unroll
        for (int d = 0; d < 32; d++) {
            float qd = __shfl_sync(FULL, q0, d);
            s0 += qd * Ks[lane][d];
            s1 += qd * Ks[lane + 32][d];
        }
        #pragma unroll
        for (int d = 0; d < 32; d++) {
            float qd = __shfl_sync(FULL, q1, d);
            s0 += qd * Ks[lane][32 + d];
            s1 += qd * Ks[lane + 32][32 + d];
        }

        float mx = fmaxf(s0, s1);
        #pragma unroll
        for (int o = 16; o > 0; o >>= 1) mx = fmaxf(mx, __shfl_xor_sync(FULL, mx, o));
        float p0 = __expf(s0 - mx);
        float p1 = __expf(s1 - mx);
        float sm = p0 + p1;
        #pragma unroll
        for (int o = 16; o > 0; o >>= 1) sm += __shfl_xor_sync(FULL, sm, o);
        float inv = 1.0f / sm;
        p0 *= inv; p1 *= inv;

        float o0 = 0.f, o1 = 0.f;
        #pragma unroll
        for (int j = 0; j < 32; j++) {
            float pj = __shfl_sync(FULL, p0, j);
            o0 += pj * Vs[j][lane];
            o1 += pj * Vs[j][32 + lane];
        }
        #pragma unroll
        for (int j = 0; j < 32; j++) {
            float pj = __shfl_sync(FULL, p1, j);
            o0 += pj * Vs[32 + j][lane];
            o1 += pj * Vs[32 + j][32 + lane];
        }
        out[qb + lane] = o0;
        out[qb + 32 + lane] = o1;
    }
}

// ---------------- launch --------------------------------------------------
extern "C" void kernel_launch(void* const* d_in, const int* in_sizes, int n_in,
                              void* d_out, int out_size)
{
    const float* y    = (const float*)d_in[0];
    const float* media= (const float*)d_in[1];
    const unsigned int* loc = (const unsigned int*)d_in[2];
    const float* ln_w = (const float*)d_in[3];
    const float* ln_b = (const float*)d_in[4];
    const float* Wq   = (const float*)d_in[5];
    const float* Wkv  = (const float*)d_in[6];
    const float* Wout = (const float*)d_in[7];
    float* out = (float*)d_out;

    float *yn_p, *q_p, *kv_p, *attn_p;
    int* tt_p;
    cudaGetSymbolAddress((void**)&yn_p,  g_yn);
    cudaGetSymbolAddress((void**)&q_p,   g_q);
    cudaGetSymbolAddress((void**)&kv_p,  g_kv);
    cudaGetSymbolAddress((void**)&attn_p,g_attn);
    cudaGetSymbolAddress((void**)&tt_p,  g_tt);

    const int smem_bytes = SMEM_FLOATS * 4;   // 71680
    cudaFuncSetAttribute(tf32gemm, cudaFuncAttributeMaxDynamicSharedMemorySize, smem_bytes);

    // 1) LayerNorm
    ln_kernel<<<BATCH * TTOK, 256>>>(y, ln_w, ln_b, yn_p);
    // 2) text_time
    cumsum_kernel<<<1, 32>>>(loc, tt_p);
    // 3) kv = media @ Wkv   [2048, 1024] @ [1024, 2048]
    {
        dim3 grid((2 * INNER) / 128, (BATCH * JTOT) / 128);
        tf32gemm<<<grid, 256, smem_bytes>>>(media, Wkv, kv_p, BATCH * JTOT, 2 * INNER, DIMV, 1.0f);
    }
    // 4) q = (yn @ Wq) * scale   [8192, 2048] @ [2048, 1024]
    {
        dim3 grid(INNER / 128, (BATCH * TTOK) / 128);
        tf32gemm<<<grid, 256, smem_bytes>>>(yn_p, Wq, q_p, BATCH * TTOK, INNER, DIM, QSCALE);
    }
    // 5) attention
    {
        dim3 grid(NMEDIA, HEADS, BATCH);
        attn_kernel<<<grid, 256>>>(q_p, kv_p, tt_p, attn_p);
    }
    // 6) out = attn @ Wout   [8192, 1024] @ [1024, 2048]
    {
        dim3 grid(DIM / 128, (BATCH * TTOK) / 128);
        tf32gemm<<<grid, 256, smem_bytes>>>(attn_p, Wout, out, BATCH * TTOK, DIM, INNER, 1.0f);
    }
}

// round 7
// speedup vs baseline: 2.5864x; 1.0135x over previous
#include <cuda_runtime.h>
#include <cuda_bf16.h>
#include <cstdint>

// ---------------- problem constants ----------------
#define BATCH 4
#define TTOK 2048
#define DIM 2048
#define DIMV 1024
#define INNER 1024
#define HEADS 16
#define DHEAD 64
#define NMEDIA 8
#define NVIS 64
#define JTOT (NMEDIA * NVIS)   // 512
#define LN_EPS 1e-5f
#define QSCALE 0.125f          // 64^-0.5

// ---------------- scratch (static device memory; no allocs allowed) ----------
__device__ float g_yn[(size_t)BATCH * TTOK * DIM];       // tf32-rounded LN out
__device__ float g_q[(size_t)BATCH * TTOK * INNER];
__device__ float g_kv[(size_t)BATCH * JTOT * 2 * INNER];
__device__ float g_attn[(size_t)BATCH * TTOK * INNER];   // tf32-rounded attn out
__device__ int   g_tt[BATCH * TTOK];
// tf32-rounded operand copies
__device__ float g_wq[(size_t)DIM * INNER];              // scaled by QSCALE
__device__ float g_wkv[(size_t)DIMV * 2 * INNER];
__device__ float g_wout[(size_t)INNER * DIM];
__device__ float g_media[(size_t)BATCH * JTOT * DIMV];

__device__ __forceinline__ float rtf32(float x) {
    uint32_t u;
    asm("cvt.rna.tf32.f32 %0, %1;" : "=r"(u) : "f"(x));
    return __uint_as_float(u);
}

// ---------------- tf32 pre-round copy: dst = tf32(alpha * src) -------------
__global__ void round_kernel(const float* __restrict__ src, float* __restrict__ dst,
                             int n4, float alpha)
{
    int i = blockIdx.x * blockDim.x + threadIdx.x;
    if (i < n4) {
        float4 v = ((const float4*)src)[i];
        v.x = rtf32(alpha * v.x);
        v.y = rtf32(alpha * v.y);
        v.z = rtf32(alpha * v.z);
        v.w = rtf32(alpha * v.w);
        ((float4*)dst)[i] = v;
    }
}

// ---------------- LayerNorm (writes tf32-rounded output) ----------------
__global__ void ln_kernel(const float* __restrict__ y,
                          const float* __restrict__ w,
                          const float* __restrict__ bb,
                          float* __restrict__ yn)
{
    long row = blockIdx.x;
    const float* x = y + row * DIM;
    float sum = 0.f, sq = 0.f;
    for (int i = threadIdx.x; i < DIM; i += 256) {
        float v = x[i];
        sum += v; sq += v * v;
    }
    __shared__ float s1[256], s2[256];
    s1[threadIdx.x] = sum; s2[threadIdx.x] = sq;
    __syncthreads();
    for (int o = 128; o > 0; o >>= 1) {
        if (threadIdx.x < o) { s1[threadIdx.x] += s1[threadIdx.x + o]; s2[threadIdx.x] += s2[threadIdx.x + o]; }
        __syncthreads();
    }
    float mu = s1[0] * (1.0f / DIM);
    float var = s2[0] * (1.0f / DIM) - mu * mu;
    float rstd = rsqrtf(var + LN_EPS);
    float* o = yn + row * DIM;
    for (int i = threadIdx.x; i < DIM; i += 256)
        o[i] = rtf32((x[i] - mu) * rstd * w[i] + bb[i]);
}

// ---------------- text_time = cumsum(media_locations) ----------------
__global__ void cumsum_kernel(const unsigned int* __restrict__ loc, int* __restrict__ tt)
{
    int b = threadIdx.x;
    if (b < BATCH) {
        int s = 0;
        for (int t = 0; t < TTOK; t++) {
            s += (loc[b * TTOK + t] != 0u) ? 1 : 0;
            tt[b * TTOK + t] = s;
        }
    }
}

// ---------------- tf32 tensor-core GEMM -----------------------------------
// C[M,N] = A[M,K] @ B[K,N]; A and B are PRE-ROUNDED tf32 (fp32 bit layout),
// so the inner loop feeds raw 32-bit LDS values straight into the MMA.
// 128x128 CTA tile, K-tile 32, 8 warps in 2x4, 64x32 per warp.

#define SA 36           // A smem row stride (floats)
#define SB 136          // B smem row stride (floats)
#define A_BUF (128 * SA)
#define B_BUF (32 * SB)
#define SMEM_FLOATS (2 * (A_BUF + B_BUF))   // 17920 floats = 71680 B

#define CP_ASYNC16(s, g) asm volatile("cp.async.cg.shared.global [%0], [%1], 16;\n" :: "r"(s), "l"(g))
#define CP_COMMIT()      asm volatile("cp.async.commit_group;\n")
#define CP_WAIT0()       asm volatile("cp.async.wait_group 0;\n" ::: "memory")

__global__ __launch_bounds__(256, 2)
void tf32gemm(const float* __restrict__ A, const float* __restrict__ B,
              float* __restrict__ C, int M, int N, int K)
{
    extern __shared__ float sm[];
    const int tid  = threadIdx.x;
    const int warp = tid >> 5, lane = tid & 31;
    const int g    = lane >> 2, tig = lane & 3;
    const int wm   = (warp >> 2) * 64;
    const int wn   = (warp & 3) * 32;
    const long bm  = (long)blockIdx.y * 128;
    const long bn  = (long)blockIdx.x * 128;

    float acc[4][4][4];
    #pragma unroll
    for (int i = 0; i < 4; i++)
        #pragma unroll
        for (int j = 0; j < 4; j++)
            #pragma unroll
            for (int c = 0; c < 4; c++) acc[i][j][c] = 0.f;

    const int nt = K / 32;

    auto loadTile = [&](int kt, int buf) {
        const float* Ag = A + bm * K + (long)kt * 32;
        const float* Bg = B + (long)kt * 32 * N + bn;
        float* sA = sm + buf * A_BUF;
        float* sB = sm + 2 * A_BUF + buf * B_BUF;
        #pragma unroll
        for (int t = 0; t < 4; t++) {
            int i = tid + t * 256;
            int r = i >> 3, c = (i & 7) * 4;
            uint32_t sa = (uint32_t)__cvta_generic_to_shared(sA + r * SA + c);
            CP_ASYNC16(sa, Ag + (long)r * K + c);
        }
        #pragma unroll
        for (int t = 0; t < 4; t++) {
            int i = tid + t * 256;
            int r = i >> 5, c = (i & 31) * 4;
            uint32_t sb = (uint32_t)__cvta_generic_to_shared(sB + r * SB + c);
            CP_ASYNC16(sb, Bg + (long)r * N + c);
        }
    };

    loadTile(0, 0);
    CP_COMMIT();

    int buf = 0;
    for (int kt = 0; kt < nt; kt++) {
        CP_WAIT0();
        __syncthreads();
        if (kt + 1 < nt) { loadTile(kt + 1, buf ^ 1); CP_COMMIT(); }

        const uint32_t* sA = (const uint32_t*)(sm + buf * A_BUF);
        const uint32_t* sB = (const uint32_t*)(sm + 2 * A_BUF + buf * B_BUF);

        #pragma unroll
        for (int ks = 0; ks < 4; ks++) {
            const int k0 = ks * 8;
            uint32_t af[4][4], bf[4][2];
            #pragma unroll
            for (int mi = 0; mi < 4; mi++) {
                const uint32_t* ar = sA + (wm + mi * 16 + g) * SA + k0;
                af[mi][0] = ar[tig];
                af[mi][2] = ar[tig + 4];
                const uint32_t* ar2 = ar + 8 * SA;
                af[mi][1] = ar2[tig];
                af[mi][3] = ar2[tig + 4];
            }
            #pragma unroll
            for (int ni = 0; ni < 4; ni++) {
                const uint32_t* bc = sB + (k0 + tig) * SB + wn + ni * 8 + g;
                bf[ni][0] = bc[0];
                bf[ni][1] = bc[4 * SB];
            }
            #pragma unroll
            for (int mi = 0; mi < 4; mi++)
                #pragma unroll
                for (int ni = 0; ni < 4; ni++) {
                    asm volatile(
                        "mma.sync.aligned.m16n8k8.row.col.f32.tf32.tf32.f32 "
                        "{%0,%1,%2,%3}, {%4,%5,%6,%7}, {%8,%9}, {%0,%1,%2,%3};"
                        : "+f"(acc[mi][ni][0]), "+f"(acc[mi][ni][1]),
                          "+f"(acc[mi][ni][2]), "+f"(acc[mi][ni][3])
                        : "r"(af[mi][0]), "r"(af[mi][1]), "r"(af[mi][2]), "r"(af[mi][3]),
                          "r"(bf[ni][0]), "r"(bf[ni][1]));
                }
        }
        __syncthreads();
        buf ^= 1;
    }

    #pragma unroll
    for (int mi = 0; mi < 4; mi++) {
        long r0 = bm + wm + mi * 16 + g;
        #pragma unroll
        for (int ni = 0; ni < 4; ni++) {
            long c0 = bn + wn + ni * 8 + tig * 2;
            float2 v0 = { acc[mi][ni][0], acc[mi][ni][1] };
            float2 v1 = { acc[mi][ni][2], acc[mi][ni][3] };
            *(float2*)&C[r0 * N + c0]       = v0;
            *(float2*)&C[(r0 + 8) * N + c0] = v1;
        }
    }
}

// ---------------- masked attention (writes tf32-rounded output) ------------
__global__ __launch_bounds__(256)
void attn_kernel(const float* __restrict__ q, const float* __restrict__ kv,
                 const int* __restrict__ tt, float* __restrict__ out)
{
    __shared__ float Ks[64][65];
    __shared__ float Vs[64][65];
    int m = blockIdx.x;
    int h = blockIdx.y;
    int b = blockIdx.z;
    int tid = threadIdx.x;

    const float* kvb = kv + (long)b * JTOT * (2 * INNER);
    for (int idx = tid; idx < 64 * 64; idx += 256) {
        int j = idx >> 6, d = idx & 63;
        long base = (long)(m * 64 + j) * (2 * INNER) + h * DHEAD + d;
        Ks[j][d] = kvb[base];
        Vs[j][d] = kvb[base + INNER];
    }
    __syncthreads();

    int warp = tid >> 5, lane = tid & 31;
    const unsigned FULL = 0xffffffffu;

    for (int t = warp; t < TTOK; t += 8) {
        int t_time = tt[b * TTOK + t];
        bool empty = (t_time < 1 || t_time > NMEDIA);
        long qb = ((long)(b * TTOK + t)) * INNER + h * DHEAD;

        if (empty) {
            if (m == 0) {
                float o0 = 0.f, o1 = 0.f;
                for (int j = 0; j < JTOT; j++) {
                    o0 += kvb[(long)j * (2 * INNER) + INNER + h * DHEAD + lane];
                    o1 += kvb[(long)j * (2 * INNER) + INNER + h * DHEAD + 32 + lane];
                }
                out[qb + lane] = rtf32(o0 * (1.0f / JTOT));
                out[qb + 32 + lane] = rtf32(o1 * (1.0f / JTOT));
            }
            continue;
        }
        if (t_time != m + 1) continue;

        float q0 = q[qb + lane];
        float q1 = q[qb + 32 + lane];

        float s0 = 0.f, s1 = 0.f;
        #pragma unroll
        for (int d = 0; d < 32; d++) {
            float qd = __shfl_sync(FULL, q0, d);
            s0 += qd * Ks[lane][d];
            s1 += qd * Ks[lane + 32][d];
        }
        #pragma unroll
        for (int d = 0; d < 32; d++) {
            float qd = __shfl_sync(FULL, q1, d);
            s0 += qd * Ks[lane][32 + d];
            s1 += qd * Ks[lane + 32][32 + d];
        }

        float mx = fmaxf(s0, s1);
        #pragma unroll
        for (int o = 16; o > 0; o >>= 1) mx = fmaxf(mx, __shfl_xor_sync(FULL, mx, o));
        float p0 = __expf(s0 - mx);
        float p1 = __expf(s1 - mx);
        float sm = p0 + p1;
        #pragma unroll
        for (int o = 16; o > 0; o >>= 1) sm += __shfl_xor_sync(FULL, sm, o);
        float inv = 1.0f / sm;
        p0 *= inv; p1 *= inv;

        float o0 = 0.f, o1 = 0.f;
        #pragma unroll
        for (int j = 0; j < 32; j++) {
            float pj = __shfl_sync(FULL, p0, j);
            o0 += pj * Vs[j][lane];
            o1 += pj * Vs[j][32 + lane];
        }
        #pragma unroll
        for (int j = 0; j < 32; j++) {
            float pj = __shfl_sync(FULL, p1, j);
            o0 += pj * Vs[32 + j][lane];
            o1 += pj * Vs[32 + j][32 + lane];
        }
        out[qb + lane] = rtf32(o0);
        out[qb + 32 + lane] = rtf32(o1);
    }
}

// ---------------- launch --------------------------------------------------
extern "C" void kernel_launch(void* const* d_in, const int* in_sizes, int n_in,
                              void* d_out, int out_size)
{
    const float* y    = (const float*)d_in[0];
    const float* media= (const float*)d_in[1];
    const unsigned int* loc = (const unsigned int*)d_in[2];
    const float* ln_w = (const float*)d_in[3];
    const float* ln_b = (const float*)d_in[4];
    const float* Wq   = (const float*)d_in[5];
    const float* Wkv  = (const float*)d_in[6];
    const float* Wout = (const float*)d_in[7];
    float* out = (float*)d_out;

    float *yn_p, *q_p, *kv_p, *attn_p, *wq_p, *wkv_p, *wout_p, *media_p;
    int* tt_p;
    cudaGetSymbolAddress((void**)&yn_p,   g_yn);
    cudaGetSymbolAddress((void**)&q_p,    g_q);
    cudaGetSymbolAddress((void**)&kv_p,   g_kv);
    cudaGetSymbolAddress((void**)&attn_p, g_attn);
    cudaGetSymbolAddress((void**)&tt_p,   g_tt);
    cudaGetSymbolAddress((void**)&wq_p,   g_wq);
    cudaGetSymbolAddress((void**)&wkv_p,  g_wkv);
    cudaGetSymbolAddress((void**)&wout_p, g_wout);
    cudaGetSymbolAddress((void**)&media_p,g_media);

    const int smem_bytes = SMEM_FLOATS * 4;
    cudaFuncSetAttribute(tf32gemm, cudaFuncAttributeMaxDynamicSharedMemorySize, smem_bytes);

    // 0) pre-round operands to tf32 (QSCALE folded into Wq)
    {
        int n4;
        n4 = (DIM * INNER) / 4;
        round_kernel<<<(n4 + 255) / 256, 256>>>(Wq, wq_p, n4, QSCALE);
        n4 = (DIMV * 2 * INNER) / 4;
        round_kernel<<<(n4 + 255) / 256, 256>>>(Wkv, wkv_p, n4, 1.0f);
        n4 = (INNER * DIM) / 4;
        round_kernel<<<(n4 + 255) / 256, 256>>>(Wout, wout_p, n4, 1.0f);
        n4 = (BATCH * JTOT * DIMV) / 4;
        round_kernel<<<(n4 + 255) / 256, 256>>>(media, media_p, n4, 1.0f);
    }
    // 1) LayerNorm (tf32-rounded output)
    ln_kernel<<<BATCH * TTOK, 256>>>(y, ln_w, ln_b, yn_p);
    // 2) text_time
    cumsum_kernel<<<1, 32>>>(loc, tt_p);
    // 3) kv = media @ Wkv
    {
        dim3 grid((2 * INNER) / 128, (BATCH * JTOT) / 128);
        tf32gemm<<<grid, 256, smem_bytes>>>(media_p, wkv_p, kv_p, BATCH * JTOT, 2 * INNER, DIMV);
    }
    // 4) q = yn @ (QSCALE*Wq)
    {
        dim3 grid(INNER / 128, (BATCH * TTOK) / 128);
        tf32gemm<<<grid, 256, smem_bytes>>>(yn_p, wq_p, q_p, BATCH * TTOK, INNER, DIM);
    }
    // 5) attention (tf32-rounded output)
    {
        dim3 grid(NMEDIA, HEADS, BATCH);
        attn_kernel<<<grid, 256>>>(q_p, kv_p, tt_p, attn_p);
    }
    // 6) out = attn @ Wout
    {
        dim3 grid(DIM / 128, (BATCH * TTOK) / 128);
        tf32gemm<<<grid, 256, smem_bytes>>>(attn_p, wout_p, out, BATCH * TTOK, DIM, INNER);
    }
}

// round 14
// speedup vs baseline: 3.6579x; 1.4143x over previous
#include <cuda_runtime.h>
#include <cuda_fp16.h>
#include <cstdint>

// ---------------- problem constants ----------------
#define BATCH 4
#define TTOK 2048
#define DIM 2048
#define DIMV 1024
#define INNER 1024
#define HEADS 16
#define DHEAD 64
#define NMEDIA 8
#define NVIS 64
#define JTOT (NMEDIA * NVIS)   // 512
#define LN_EPS 1e-5f
#define QSCALE 0.125f

// ---------------- scratch ----------------
__device__ __half g_yn[(size_t)BATCH * TTOK * DIM];        // fp16 LN out
__device__ float  g_q[(size_t)BATCH * TTOK * INNER];       // fp32 (attn reads)
__device__ float  g_kv[(size_t)BATCH * JTOT * 2 * INNER];  // fp32 (attn reads)
__device__ __half g_attn[(size_t)BATCH * TTOK * INNER];    // fp16 attn out
__device__ int    g_tt[BATCH * TTOK];
// fp16 TRANSPOSED weights (rows = N, cols = K) + fp16 media
__device__ __half g_wqT[(size_t)INNER * DIM];              // QSCALE folded
__device__ __half g_wkvT[(size_t)(2 * INNER) * DIMV];
__device__ __half g_woutT[(size_t)DIM * INNER];
__device__ __half g_media[(size_t)BATCH * JTOT * DIMV];

// ---------------- helpers ----------------
#define SMEM_SWIZZLE_128B(o) ((o) ^ (((o) >> 3) & 0x70))
#define CP_ASYNC16(s, g) asm volatile("cp.async.cg.shared.global [%0], [%1], 16;\n" :: "r"(s), "l"(g))
#define CP_COMMIT()      asm volatile("cp.async.commit_group;\n")
#define CP_WAIT0()       asm volatile("cp.async.wait_group 0;\n" ::: "memory")

#define LDMATRIX_X4(r0, r1, r2, r3, addr) \
    asm volatile("ldmatrix.sync.aligned.m8n8.x4.shared.b16 {%0,%1,%2,%3}, [%4];" \
                 : "=r"(r0), "=r"(r1), "=r"(r2), "=r"(r3) : "r"(addr))

#define MMA16816(c, a, b0v, b1v) \
    asm volatile("mma.sync.aligned.m16n8k16.row.col.f32.f16.f16.f32 " \
                 "{%0,%1,%2,%3}, {%4,%5,%6,%7}, {%8,%9}, {%0,%1,%2,%3};" \
                 : "+f"((c)[0]), "+f"((c)[1]), "+f"((c)[2]), "+f"((c)[3]) \
                 : "r"((a)[0]), "r"((a)[1]), "r"((a)[2]), "r"((a)[3]), \
                   "r"(b0v), "r"(b1v))

// ---------------- fp16 tensor-core GEMM -----------------------------------
// C[M,N](fp32) = A[M,K](fp16, row-major) @ Bt[N,K](fp16, row-major)^T
// 128x128 CTA tile, KT=64 (128B rows, SW128 swizzle, ldmatrix fragments),
// cp.async double-buffered. 8 warps in 2x4, 64x32 per warp.
#define KT 64
#define TILE_B 16384                       // 128 rows x 128 bytes
#define SM_B_OFF (2 * TILE_B)
#define SM_TOTAL (4 * TILE_B)              // 65536

__global__ __launch_bounds__(256)
void hgemm(const __half* __restrict__ A, const __half* __restrict__ Bt,
           float* __restrict__ C, int M, int N, int K)
{
    extern __shared__ char smem[];
    uint32_t smem_base;
    asm("{ .reg .u64 t; cvta.to.shared.u64 t, %1; cvt.u32.u64 %0, t; }"
        : "=r"(smem_base) : "l"(smem));

    const int tid  = threadIdx.x;
    const int warp = tid >> 5, lane = tid & 31;
    const int g    = lane >> 2, tig = lane & 3;
    const int wm   = (warp >> 2) * 64;     // 0 / 64
    const int wn   = (warp & 3) * 32;      // 0..96
    const long bm  = (long)blockIdx.y * 128;
    const long bn  = (long)blockIdx.x * 128;

    float acc[4][4][4];
    #pragma unroll
    for (int i = 0; i < 4; i++)
        #pragma unroll
        for (int j = 0; j < 4; j++)
            #pragma unroll
            for (int c = 0; c < 4; c++) acc[i][j][c] = 0.f;

    const int nt = K / KT;

    auto loadTile = [&](int kt, int buf) {
        const __half* Ag = A + bm * K + (long)kt * KT;
        const __half* Bg = Bt + bn * K + (long)kt * KT;
        uint32_t sA = smem_base + buf * TILE_B;
        uint32_t sB = smem_base + SM_B_OFF + buf * TILE_B;
        #pragma unroll
        for (int t = 0; t < 4; t++) {
            int i = tid + t * 256;                 // 0..1023
            int r = i >> 3, c = (i & 7) * 16;      // byte col in 128B row
            uint32_t off = SMEM_SWIZZLE_128B(r * 128 + c);
            CP_ASYNC16(sA + off, (const char*)Ag + (long)r * K * 2 + c);
        }
        #pragma unroll
        for (int t = 0; t < 4; t++) {
            int i = tid + t * 256;
            int r = i >> 3, c = (i & 7) * 16;
            uint32_t off = SMEM_SWIZZLE_128B(r * 128 + c);
            CP_ASYNC16(sB + off, (const char*)Bg + (long)r * K * 2 + c);
        }
    };

    loadTile(0, 0);
    CP_COMMIT();

    // per-lane ldmatrix row/chunk components (fixed across tiles)
    const int lrow = lane & 15;            // row within 16-row group
    const int lchunk = (lane >> 4) * 16;   // 16B chunk (k halves 0-7 / 8-15)

    for (int kt = 0; kt < nt; kt++) {
        int buf = kt & 1;
        CP_WAIT0();
        __syncthreads();
        if (kt + 1 < nt) { loadTile(kt + 1, buf ^ 1); CP_COMMIT(); }

        uint32_t sA = smem_base + buf * TILE_B;
        uint32_t sB = smem_base + SM_B_OFF + buf * TILE_B;

        #pragma unroll
        for (int ks = 0; ks < 4; ks++) {
            const int kb = ks * 32;        // byte offset of k16 group in row
            uint32_t a[4][4], b[2][4];
            #pragma unroll
            for (int mi = 0; mi < 4; mi++) {
                int row = wm + mi * 16 + lrow;
                uint32_t off = SMEM_SWIZZLE_128B(row * 128 + kb + lchunk);
                LDMATRIX_X4(a[mi][0], a[mi][1], a[mi][2], a[mi][3], sA + off);
            }
            #pragma unroll
            for (int nj = 0; nj < 2; nj++) {
                int row = wn + nj * 16 + lrow;
                uint32_t off = SMEM_SWIZZLE_128B(row * 128 + kb + lchunk);
                LDMATRIX_X4(b[nj][0], b[nj][1], b[nj][2], b[nj][3], sB + off);
            }
            #pragma unroll
            for (int mi = 0; mi < 4; mi++)
                #pragma unroll
                for (int nj = 0; nj < 2; nj++) {
                    MMA16816(acc[mi][nj * 2],     a[mi], b[nj][0], b[nj][2]);
                    MMA16816(acc[mi][nj * 2 + 1], a[mi], b[nj][1], b[nj][3]);
                }
        }
        __syncthreads();
    }

    #pragma unroll
    for (int mi = 0; mi < 4; mi++) {
        long r0 = bm + wm + mi * 16 + g;
        #pragma unroll
        for (int ni = 0; ni < 4; ni++) {
            long c0 = bn + wn + ni * 8 + tig * 2;
            float2 v0 = { acc[mi][ni][0], acc[mi][ni][1] };
            float2 v1 = { acc[mi][ni][2], acc[mi][ni][3] };
            *(float2*)&C[r0 * N + c0]       = v0;
            *(float2*)&C[(r0 + 8) * N + c0] = v1;
        }
    }
}

// ---------------- transpose + fp16: dst[N][K] = h(alpha * src[K][N]) -------
__global__ void transpose_half(const float* __restrict__ src, __half* __restrict__ dst,
                               int K, int N, float alpha)
{
    __shared__ float t[32][33];
    int k0 = blockIdx.x * 32, n0 = blockIdx.y * 32;
    int tx = threadIdx.x, ty = threadIdx.y;   // (32, 8)
    #pragma unroll
    for (int j = 0; j < 32; j += 8)
        t[ty + j][tx] = src[(long)(k0 + ty + j) * N + n0 + tx];
    __syncthreads();
    #pragma unroll
    for (int j = 0; j < 32; j += 8)
        dst[(long)(n0 + ty + j) * K + k0 + tx] = __float2half(alpha * t[tx][ty + j]);
}

// ---------------- fp16 copy (media) ----------------
__global__ void half_kernel(const float* __restrict__ src, __half* __restrict__ dst, int n4)
{
    int i = blockIdx.x * blockDim.x + threadIdx.x;
    if (i < n4) {
        float4 v = ((const float4*)src)[i];
        __half2 h0 = __floats2half2_rn(v.x, v.y);
        __half2 h1 = __floats2half2_rn(v.z, v.w);
        ((__half2*)dst)[i * 2]     = h0;
        ((__half2*)dst)[i * 2 + 1] = h1;
    }
}

// ---------------- LayerNorm (fp16 out) ----------------
__global__ void ln_kernel(const float* __restrict__ y,
                          const float* __restrict__ w,
                          const float* __restrict__ bb,
                          __half* __restrict__ yn)
{
    long row = blockIdx.x;
    const float* x = y + row * DIM;
    float sum = 0.f, sq = 0.f;
    for (int i = threadIdx.x; i < DIM; i += 256) {
        float v = x[i];
        sum += v; sq += v * v;
    }
    __shared__ float s1[256], s2[256];
    s1[threadIdx.x] = sum; s2[threadIdx.x] = sq;
    __syncthreads();
    for (int o = 128; o > 0; o >>= 1) {
        if (threadIdx.x < o) { s1[threadIdx.x] += s1[threadIdx.x + o]; s2[threadIdx.x] += s2[threadIdx.x + o]; }
        __syncthreads();
    }
    float mu = s1[0] * (1.0f / DIM);
    float var = s2[0] * (1.0f / DIM) - mu * mu;
    float rstd = rsqrtf(var + LN_EPS);
    __half* o = yn + row * DIM;
    for (int i = threadIdx.x; i < DIM; i += 256)
        o[i] = __float2half((x[i] - mu) * rstd * w[i] + bb[i]);
}

// ---------------- cumsum ----------------
__global__ void cumsum_kernel(const unsigned int* __restrict__ loc, int* __restrict__ tt)
{
    int b = threadIdx.x;
    if (b < BATCH) {
        int s = 0;
        for (int t = 0; t < TTOK; t++) {
            s += (loc[b * TTOK + t] != 0u) ? 1 : 0;
            tt[b * TTOK + t] = s;
        }
    }
}

// ---------------- masked attention (fp16 out) ----------------
__global__ __launch_bounds__(256)
void attn_kernel(const float* __restrict__ q, const float* __restrict__ kv,
                 const int* __restrict__ tt, __half* __restrict__ out)
{
    __shared__ float Ks[64][65];
    __shared__ float Vs[64][65];
    int m = blockIdx.x;
    int h = blockIdx.y;
    int b = blockIdx.z;
    int tid = threadIdx.x;

    const float* kvb = kv + (long)b * JTOT * (2 * INNER);
    for (int idx = tid; idx < 64 * 64; idx += 256) {
        int j = idx >> 6, d = idx & 63;
        long base = (long)(m * 64 + j) * (2 * INNER) + h * DHEAD + d;
        Ks[j][d] = kvb[base];
        Vs[j][d] = kvb[base + INNER];
    }
    __syncthreads();

    int warp = tid >> 5, lane = tid & 31;
    const unsigned FULL = 0xffffffffu;

    for (int t = warp; t < TTOK; t += 8) {
        int t_time = tt[b * TTOK + t];
        bool empty = (t_time < 1 || t_time > NMEDIA);
        long qb = ((long)(b * TTOK + t)) * INNER + h * DHEAD;

        if (empty) {
            if (m == 0) {
                float o0 = 0.f, o1 = 0.f;
                for (int j = 0; j < JTOT; j++) {
                    o0 += kvb[(long)j * (2 * INNER) + INNER + h * DHEAD + lane];
                    o1 += kvb[(long)j * (2 * INNER) + INNER + h * DHEAD + 32 + lane];
                }
                out[qb + lane] = __float2half(o0 * (1.0f / JTOT));
                out[qb + 32 + lane] = __float2half(o1 * (1.0f / JTOT));
            }
            continue;
        }
        if (t_time != m + 1) continue;

        float q0 = q[qb + lane];
        float q1 = q[qb + 32 + lane];

        float s0 = 0.f, s1 = 0.f;
        #pragma unroll
        for (int d = 0; d < 32; d++) {
            float qd = __shfl_sync(FULL, q0, d);
            s0 += qd * Ks[lane][d];
            s1 += qd * Ks[lane + 32][d];
        }
        #pragma unroll
        for (int d = 0; d < 32; d++) {
            float qd = __shfl_sync(FULL, q1, d);
            s0 += qd * Ks[lane][32 + d];
            s1 += qd * Ks[lane + 32][32 + d];
        }

        float mx = fmaxf(s0, s1);
        #pragma unroll
        for (int o = 16; o > 0; o >>= 1) mx = fmaxf(mx, __shfl_xor_sync(FULL, mx, o));
        float p0 = __expf(s0 - mx);
        float p1 = __expf(s1 - mx);
        float sm = p0 + p1;
        #pragma unroll
        for (int o = 16; o > 0; o >>= 1) sm += __shfl_xor_sync(FULL, sm, o);
        float inv = 1.0f / sm;
        p0 *= inv; p1 *= inv;

        float o0 = 0.f, o1 = 0.f;
        #pragma unroll
        for (int j = 0; j < 32; j++) {
            float pj = __shfl_sync(FULL, p0, j);
            o0 += pj * Vs[j][lane];
            o1 += pj * Vs[j][32 + lane];
        }
        #pragma unroll
        for (int j = 0; j < 32; j++) {
            float pj = __shfl_sync(FULL, p1, j);
            o0 += pj * Vs[32 + j][lane];
            o1 += pj * Vs[32 + j][32 + lane];
        }
        out[qb + lane] = __float2half(o0);
        out[qb + 32 + lane] = __float2half(o1);
    }
}

// ---------------- launch --------------------------------------------------
extern "C" void kernel_launch(void* const* d_in, const int* in_sizes, int n_in,
                              void* d_out, int out_size)
{
    const float* y    = (const float*)d_in[0];
    const float* media= (const float*)d_in[1];
    const unsigned int* loc = (const unsigned int*)d_in[2];
    const float* ln_w = (const float*)d_in[3];
    const float* ln_b = (const float*)d_in[4];
    const float* Wq   = (const float*)d_in[5];
    const float* Wkv  = (const float*)d_in[6];
    const float* Wout = (const float*)d_in[7];
    float* out = (float*)d_out;

    __half *yn_p, *attn_p, *wqT_p, *wkvT_p, *woutT_p, *media_p;
    float *q_p, *kv_p;
    int* tt_p;
    cudaGetSymbolAddress((void**)&yn_p,    g_yn);
    cudaGetSymbolAddress((void**)&q_p,     g_q);
    cudaGetSymbolAddress((void**)&kv_p,    g_kv);
    cudaGetSymbolAddress((void**)&attn_p,  g_attn);
    cudaGetSymbolAddress((void**)&tt_p,    g_tt);
    cudaGetSymbolAddress((void**)&wqT_p,   g_wqT);
    cudaGetSymbolAddress((void**)&wkvT_p,  g_wkvT);
    cudaGetSymbolAddress((void**)&woutT_p, g_woutT);
    cudaGetSymbolAddress((void**)&media_p, g_media);

    cudaFuncSetAttribute(hgemm, cudaFuncAttributeMaxDynamicSharedMemorySize, SM_TOTAL);

    // 0) weight transpose + fp16 (QSCALE folded into WqT); media -> fp16
    {
        dim3 thr(32, 8);
        transpose_half<<<dim3(DIM / 32, INNER / 32), thr>>>(Wq, wqT_p, DIM, INNER, QSCALE);
        transpose_half<<<dim3(DIMV / 32, (2 * INNER) / 32), thr>>>(Wkv, wkvT_p, DIMV, 2 * INNER, 1.0f);
        transpose_half<<<dim3(INNER / 32, DIM / 32), thr>>>(Wout, woutT_p, INNER, DIM, 1.0f);
        int n4 = (BATCH * JTOT * DIMV) / 4;
        half_kernel<<<(n4 + 255) / 256, 256>>>(media, media_p, n4);
    }
    // 1) LayerNorm (fp16 out)
    ln_kernel<<<BATCH * TTOK, 256>>>(y, ln_w, ln_b, yn_p);
    // 2) text_time
    cumsum_kernel<<<1, 32>>>(loc, tt_p);
    // 3) kv = media @ Wkv   (M=2048, N=2048, K=1024)
    hgemm<<<dim3((2 * INNER) / 128, (BATCH * JTOT) / 128), 256, SM_TOTAL>>>(
        media_p, wkvT_p, kv_p, BATCH * JTOT, 2 * INNER, DIMV);
    // 4) q = yn @ (QSCALE*Wq)   (M=8192, N=1024, K=2048)
    hgemm<<<dim3(INNER / 128, (BATCH * TTOK) / 128), 256, SM_TOTAL>>>(
        yn_p, wqT_p, q_p, BATCH * TTOK, INNER, DIM);
    // 5) attention (fp16 out)
    attn_kernel<<<dim3(NMEDIA, HEADS, BATCH), 256>>>(q_p, kv_p, tt_p, attn_p);
    // 6) out = attn @ Wout   (M=8192, N=2048, K=1024)
    hgemm<<<dim3(DIM / 128, (BATCH * TTOK) / 128), 256, SM_TOTAL>>>(
        attn_p, woutT_p, out, BATCH * TTOK, DIM, INNER);
}